// round 1
// baseline (speedup 1.0000x reference)
#include <cuda_runtime.h>
#include <math.h>

#define Bsz 4
#define T   2048
#define D   1024
#define H   16
#define HS  64
#define BT  (Bsz*T)      // 8192
#define D4  (4*D)        // 4096

// ---------------- scratch (device globals; no allocation allowed) ----------
__device__ float g_xn1[BT*D];   // xn1, then reused for attention output
__device__ float g_q  [BT*D];   // q, then reused for xn2
__device__ float g_k  [BT*D];
__device__ float g_v  [BT*D];
__device__ float g_x1 [BT*D];   // x after attention residual
__device__ float g_h1 [(size_t)BT*D4]; // FFN hidden

// ---------------- LayerNorm: one block per row, D=1024 ---------------------
__global__ __launch_bounds__(256)
void ln_kernel(const float* __restrict__ x, const float* __restrict__ g,
               const float* __restrict__ b, float* __restrict__ out) {
    int row = blockIdx.x;
    int tid = threadIdx.x;
    const float4* xr = (const float4*)(x + (size_t)row * D);
    float4 v4 = xr[tid];
    float s  = v4.x + v4.y + v4.z + v4.w;
    float ss = v4.x*v4.x + v4.y*v4.y + v4.z*v4.z + v4.w*v4.w;
    #pragma unroll
    for (int off = 16; off; off >>= 1) {
        s  += __shfl_xor_sync(0xffffffffu, s,  off);
        ss += __shfl_xor_sync(0xffffffffu, ss, off);
    }
    __shared__ float rs[8], rss[8];
    int warp = tid >> 5, lane = tid & 31;
    if (lane == 0) { rs[warp] = s; rss[warp] = ss; }
    __syncthreads();
    float tot = 0.f, tot2 = 0.f;
    #pragma unroll
    for (int i = 0; i < 8; i++) { tot += rs[i]; tot2 += rss[i]; }
    float mu  = tot * (1.0f / D);
    float var = tot2 * (1.0f / D) - mu * mu;
    float rstd = rsqrtf(var + 1e-5f);
    float4 g4 = ((const float4*)g)[tid];
    float4 b4 = ((const float4*)b)[tid];
    float4 o4;
    o4.x = (v4.x - mu) * rstd * g4.x + b4.x;
    o4.y = (v4.y - mu) * rstd * g4.y + b4.y;
    o4.z = (v4.z - mu) * rstd * g4.z + b4.z;
    o4.w = (v4.w - mu) * rstd * g4.w + b4.w;
    ((float4*)(out + (size_t)row * D))[tid] = o4;
}

// ---------------- SGEMM: C[M,N] = op(A[M,K] @ W[K,N] (+bias)(relu)(+res)) --
// 128x128 tile, BK=8, 256 threads, 8x8 per thread. All dims divide tiles.
template<bool RELU, bool BIAS, bool RES>
__global__ __launch_bounds__(256)
void sgemm(const float* __restrict__ A, const float* __restrict__ W,
           const float* __restrict__ bias, const float* __restrict__ res,
           float* __restrict__ C, int M, int N, int K) {
    __shared__ float As[8][128];
    __shared__ float Ws[8][128];
    int m0 = blockIdx.y * 128, n0 = blockIdx.x * 128;
    int tid = threadIdx.x;
    int tr = tid >> 4, tc = tid & 15;     // 16x16 thread grid
    float acc[8][8];
    #pragma unroll
    for (int i = 0; i < 8; i++)
        #pragma unroll
        for (int j = 0; j < 8; j++) acc[i][j] = 0.f;

    for (int k0 = 0; k0 < K; k0 += 8) {
        { // load A tile 128x8, store transposed
            int row = tid >> 1, kq = (tid & 1) * 4;
            float4 a4 = *(const float4*)(A + (size_t)(m0 + row) * K + k0 + kq);
            As[kq+0][row] = a4.x; As[kq+1][row] = a4.y;
            As[kq+2][row] = a4.z; As[kq+3][row] = a4.w;
        }
        { // load W tile 8x128
            int row = tid >> 5, c4 = (tid & 31) * 4;
            *(float4*)&Ws[row][c4] =
                *(const float4*)(W + (size_t)(k0 + row) * N + n0 + c4);
        }
        __syncthreads();
        #pragma unroll
        for (int k = 0; k < 8; k++) {
            float a[8], w[8];
            *(float4*)(a)   = *(const float4*)&As[k][tr*8];
            *(float4*)(a+4) = *(const float4*)&As[k][tr*8+4];
            *(float4*)(w)   = *(const float4*)&Ws[k][tc*8];
            *(float4*)(w+4) = *(const float4*)&Ws[k][tc*8+4];
            #pragma unroll
            for (int i = 0; i < 8; i++)
                #pragma unroll
                for (int j = 0; j < 8; j++)
                    acc[i][j] = fmaf(a[i], w[j], acc[i][j]);
        }
        __syncthreads();
    }
    // epilogue
    float bv[8];
    if (BIAS) {
        #pragma unroll
        for (int j = 0; j < 8; j++) bv[j] = bias[n0 + tc*8 + j];
    }
    #pragma unroll
    for (int i = 0; i < 8; i++) {
        size_t m = (size_t)(m0 + tr*8 + i);
        float* crow = C + m * N + n0 + tc*8;
        const float* rrow = RES ? (res + m * N + n0 + tc*8) : nullptr;
        float o[8];
        #pragma unroll
        for (int j = 0; j < 8; j++) {
            float val = acc[i][j];
            if (BIAS) val += bv[j];
            if (RELU) val = fmaxf(val, 0.f);
            if (RES)  val += rrow[j];
            o[j] = val;
        }
        *(float4*)(crow)   = *(float4*)(o);
        *(float4*)(crow+4) = *(float4*)(o+4);
    }
}

// ---------------- Flash attention (fp32, causal), 64x64 tiles --------------
// q,k,v layout: [B, T, H, HS] (== [BT, D]). scale = D^-0.5 = 1/32.
#define PADR 65
__global__ __launch_bounds__(256)
void flash_kernel(const float* __restrict__ q, const float* __restrict__ k,
                  const float* __restrict__ v, float* __restrict__ o) {
    extern __shared__ float sm[];
    float* Qs = sm;                  // 64 x 65
    float* Ks = Qs + 64*PADR;
    float* Vs = Ks + 64*PADR;
    float* Ss = Vs + 64*PADR;

    int qt = blockIdx.x, h = blockIdx.y, b = blockIdx.z;
    int q0 = qt * 64;
    int tid = threadIdx.x;
    int ty = tid >> 4, tx = tid & 15;

    // load Q tile
    #pragma unroll
    for (int it = 0; it < 4; it++) {
        int idx = tid + it * 256;          // 0..1023 float4 slots
        int row = idx >> 4, c4 = (idx & 15) * 4;
        float4 qv = *(const float4*)(q + ((size_t)(b*T + q0 + row) * H + h) * HS + c4);
        Qs[row*PADR + c4+0] = qv.x; Qs[row*PADR + c4+1] = qv.y;
        Qs[row*PADR + c4+2] = qv.z; Qs[row*PADR + c4+3] = qv.w;
    }
    __syncthreads();

    float m_i[4], l_i[4], acc[4][4];
    #pragma unroll
    for (int i = 0; i < 4; i++) {
        m_i[i] = -1e30f; l_i[i] = 0.f;
        #pragma unroll
        for (int j = 0; j < 4; j++) acc[i][j] = 0.f;
    }
    const float scale = 0.03125f;  // 1024^-0.5

    for (int kt = 0; kt <= qt; kt++) {
        int k0 = kt * 64;
        // load K, V tiles
        #pragma unroll
        for (int it = 0; it < 4; it++) {
            int idx = tid + it * 256;
            int row = idx >> 4, c4 = (idx & 15) * 4;
            size_t goff = ((size_t)(b*T + k0 + row) * H + h) * HS + c4;
            float4 kv = *(const float4*)(k + goff);
            float4 vv = *(const float4*)(v + goff);
            Ks[row*PADR + c4+0] = kv.x; Ks[row*PADR + c4+1] = kv.y;
            Ks[row*PADR + c4+2] = kv.z; Ks[row*PADR + c4+3] = kv.w;
            Vs[row*PADR + c4+0] = vv.x; Vs[row*PADR + c4+1] = vv.y;
            Vs[row*PADR + c4+2] = vv.z; Vs[row*PADR + c4+3] = vv.w;
        }
        __syncthreads();

        // S = scale * Q K^T  (4x4 fragment per thread)
        float s[4][4];
        #pragma unroll
        for (int i = 0; i < 4; i++)
            #pragma unroll
            for (int j = 0; j < 4; j++) s[i][j] = 0.f;
        #pragma unroll 4
        for (int kk = 0; kk < 64; kk++) {
            float a[4], bb[4];
            #pragma unroll
            for (int i = 0; i < 4; i++) a[i]  = Qs[(ty*4+i)*PADR + kk];
            #pragma unroll
            for (int j = 0; j < 4; j++) bb[j] = Ks[(tx*4+j)*PADR + kk];
            #pragma unroll
            for (int i = 0; i < 4; i++)
                #pragma unroll
                for (int j = 0; j < 4; j++)
                    s[i][j] = fmaf(a[i], bb[j], s[i][j]);
        }
        #pragma unroll
        for (int i = 0; i < 4; i++)
            #pragma unroll
            for (int j = 0; j < 4; j++) s[i][j] *= scale;
        if (kt == qt) {  // causal mask on diagonal tile
            #pragma unroll
            for (int i = 0; i < 4; i++) {
                int qi = ty*4 + i;
                #pragma unroll
                for (int j = 0; j < 4; j++)
                    if (tx*4 + j > qi) s[i][j] = -1e30f;
            }
        }
        // online softmax per row (16 threads / row share ty)
        #pragma unroll
        for (int i = 0; i < 4; i++) {
            float rmax = s[i][0];
            #pragma unroll
            for (int j = 1; j < 4; j++) rmax = fmaxf(rmax, s[i][j]);
            #pragma unroll
            for (int off = 1; off < 16; off <<= 1)
                rmax = fmaxf(rmax, __shfl_xor_sync(0xffffffffu, rmax, off));
            float m_new = fmaxf(m_i[i], rmax);
            float alpha = __expf(m_i[i] - m_new);
            float rsum = 0.f;
            float p[4];
            #pragma unroll
            for (int j = 0; j < 4; j++) {
                p[j] = __expf(s[i][j] - m_new);
                rsum += p[j];
            }
            #pragma unroll
            for (int off = 1; off < 16; off <<= 1)
                rsum += __shfl_xor_sync(0xffffffffu, rsum, off);
            l_i[i] = l_i[i] * alpha + rsum;
            m_i[i] = m_new;
            #pragma unroll
            for (int j = 0; j < 4; j++) {
                Ss[(ty*4+i)*PADR + tx*4 + j] = p[j];
                acc[i][j] *= alpha;
            }
        }
        __syncthreads();
        // O += P @ V
        #pragma unroll 4
        for (int kk = 0; kk < 64; kk++) {
            float a[4], vv[4];
            #pragma unroll
            for (int i = 0; i < 4; i++) a[i]  = Ss[(ty*4+i)*PADR + kk];
            #pragma unroll
            for (int j = 0; j < 4; j++) vv[j] = Vs[kk*PADR + tx*4 + j];
            #pragma unroll
            for (int i = 0; i < 4; i++)
                #pragma unroll
                for (int j = 0; j < 4; j++)
                    acc[i][j] = fmaf(a[i], vv[j], acc[i][j]);
        }
        __syncthreads();
    }
    // epilogue: divide by l, write [b, t, h, hs]
    #pragma unroll
    for (int i = 0; i < 4; i++) {
        float inv = 1.0f / l_i[i];
        float* orow = o + ((size_t)(b*T + q0 + ty*4 + i) * H + h) * HS + tx*4;
        #pragma unroll
        for (int j = 0; j < 4; j++) orow[j] = acc[i][j] * inv;
    }
}

// ---------------- launch ---------------------------------------------------
extern "C" void kernel_launch(void* const* d_in, const int* in_sizes, int n_in,
                              void* d_out, int out_size) {
    const float* x   = (const float*)d_in[0];
    const float* wq  = (const float*)d_in[1];
    const float* wk  = (const float*)d_in[2];
    const float* wv  = (const float*)d_in[3];
    const float* wo  = (const float*)d_in[4];
    const float* bo  = (const float*)d_in[5];
    const float* w1  = (const float*)d_in[6];
    const float* b1  = (const float*)d_in[7];
    const float* w2  = (const float*)d_in[8];
    const float* b2  = (const float*)d_in[9];
    const float* g1  = (const float*)d_in[10];
    const float* be1 = (const float*)d_in[11];
    const float* g2  = (const float*)d_in[12];
    const float* be2 = (const float*)d_in[13];
    float* out = (float*)d_out;

    float *xn1, *q, *k, *v, *x1, *h1;
    cudaGetSymbolAddress((void**)&xn1, g_xn1);
    cudaGetSymbolAddress((void**)&q,   g_q);
    cudaGetSymbolAddress((void**)&k,   g_k);
    cudaGetSymbolAddress((void**)&v,   g_v);
    cudaGetSymbolAddress((void**)&x1,  g_x1);
    cudaGetSymbolAddress((void**)&h1,  g_h1);

    // LN1
    ln_kernel<<<BT, 256>>>(x, g1, be1, xn1);

    // QKV projections
    dim3 gqkv(D/128, BT/128);
    sgemm<false,false,false><<<gqkv, 256>>>(xn1, wq, nullptr, nullptr, q, BT, D, D);
    sgemm<false,false,false><<<gqkv, 256>>>(xn1, wk, nullptr, nullptr, k, BT, D, D);
    sgemm<false,false,false><<<gqkv, 256>>>(xn1, wv, nullptr, nullptr, v, BT, D, D);

    // Flash attention -> reuse xn1 as attention output buffer
    int smem = 4 * 64 * PADR * (int)sizeof(float);
    cudaFuncSetAttribute(flash_kernel, cudaFuncAttributeMaxDynamicSharedMemorySize, smem);
    flash_kernel<<<dim3(T/64, H, Bsz), 256, smem>>>(q, k, v, xn1);

    // Wo projection + bias + residual(x) -> x1
    sgemm<false,true,true><<<gqkv, 256>>>(xn1, wo, bo, x, x1, BT, D, D);

    // LN2 -> reuse q as xn2
    ln_kernel<<<BT, 256>>>(x1, g2, be2, q);

    // FFN up (relu(xn2 @ w1 + b1)) -> h1
    dim3 gup(D4/128, BT/128);
    sgemm<true,true,false><<<gup, 256>>>(q, w1, b1, nullptr, h1, BT, D4, D);

    // FFN down + bias + residual(x1) -> out
    dim3 gdn(D/128, BT/128);
    sgemm<false,true,true><<<gdn, 256>>>(h1, w2, b2, x1, out, BT, D, D4);
}

// round 3
// speedup vs baseline: 2.1485x; 2.1485x over previous
#include <cuda_runtime.h>
#include <cuda_bf16.h>
#include <cstdint>
#include <math.h>

#define Bsz 4
#define T   2048
#define D   1024
#define H   16
#define HS  64
#define BT  (Bsz*T)      // 8192
#define D4  (4*D)        // 4096

// ======================= scratch ============================================
__device__ __nv_bfloat16 g_xnh[BT*D], g_xnl[BT*D];        // LN out / attn out (reused)
__device__ __nv_bfloat16 g_wqkvh[(size_t)D*3*D], g_wqkvl[(size_t)D*3*D]; // [1024][3072]
__device__ __nv_bfloat16 g_woh[D*D], g_wol[D*D];          // [1024][1024]
__device__ __nv_bfloat16 g_w1h[(size_t)D*D4], g_w1l[(size_t)D*D4];  // [1024][4096]
__device__ __nv_bfloat16 g_w2h[(size_t)D4*D], g_w2l[(size_t)D4*D];  // [4096][1024]
__device__ float g_qkv[(size_t)BT*3*D];                   // fused qkv fp32 [8192][3072]
__device__ __nv_bfloat16 g_h1h[(size_t)BT*D4], g_h1l[(size_t)BT*D4];
__device__ float g_x1[BT*D];

// ======================= small asm helpers ==================================
__device__ __forceinline__ uint32_t smem_u32(const void* p) {
    uint32_t a;
    asm("{ .reg .u64 t; cvta.to.shared.u64 t, %1; cvt.u32.u64 %0, t; }"
        : "=r"(a) : "l"(p));
    return a;
}
__device__ __forceinline__ void cp16(uint32_t s, const void* g) {
    asm volatile("cp.async.cg.shared.global [%0], [%1], 16;" :: "r"(s), "l"(g));
}
#define CP_COMMIT() asm volatile("cp.async.commit_group;" ::: "memory")
#define CP_WAIT(n)  asm volatile("cp.async.wait_group %0;" :: "n"(n) : "memory")

__device__ __forceinline__ void ldsm_x4(uint32_t* r, uint32_t a) {
    asm volatile("ldmatrix.sync.aligned.m8n8.x4.shared.b16 {%0,%1,%2,%3}, [%4];"
                 : "=r"(r[0]), "=r"(r[1]), "=r"(r[2]), "=r"(r[3]) : "r"(a));
}
__device__ __forceinline__ void ldsm_x2t(uint32_t* r, uint32_t a) {
    asm volatile("ldmatrix.sync.aligned.m8n8.x2.trans.shared.b16 {%0,%1}, [%2];"
                 : "=r"(r[0]), "=r"(r[1]) : "r"(a));
}
__device__ __forceinline__ void mma_bf16(float* d, const uint32_t* a, const uint32_t* b) {
    asm volatile(
        "mma.sync.aligned.m16n8k16.row.col.f32.bf16.bf16.f32 "
        "{%0,%1,%2,%3}, {%4,%5,%6,%7}, {%8,%9}, {%0,%1,%2,%3};"
        : "+f"(d[0]), "+f"(d[1]), "+f"(d[2]), "+f"(d[3])
        : "r"(a[0]), "r"(a[1]), "r"(a[2]), "r"(a[3]), "r"(b[0]), "r"(b[1]));
}

// ================= weight bf16 hi/lo split (no transpose) ===================
// W fp32 [K][n_src] -> Th/Tl bf16 at [K][dst_stride] with column offset.
__global__ __launch_bounds__(256)
void wsplit(const float* __restrict__ W, __nv_bfloat16* __restrict__ Th,
            __nv_bfloat16* __restrict__ Tl, int n_src, int dst_stride, int col_off) {
    size_t p4 = ((size_t)blockIdx.x * 256 + threadIdx.x) * 4;
    float4 w = *(const float4*)(W + p4);
    int k = (int)(p4 / n_src), n = (int)(p4 % n_src);
    size_t o = (size_t)k * dst_stride + col_off + n;
    float vv[4] = {w.x, w.y, w.z, w.w};
    #pragma unroll
    for (int j = 0; j < 4; j += 2) {
        __nv_bfloat16 h0 = __float2bfloat16(vv[j]);
        __nv_bfloat16 h1 = __float2bfloat16(vv[j+1]);
        __nv_bfloat16 l0 = __float2bfloat16(vv[j]   - __bfloat162float(h0));
        __nv_bfloat16 l1 = __float2bfloat16(vv[j+1] - __bfloat162float(h1));
        *(__nv_bfloat162*)(Th + o + j) = __nv_bfloat162(h0, h1);
        *(__nv_bfloat162*)(Tl + o + j) = __nv_bfloat162(l0, l1);
    }
}

// ================= LayerNorm with fused bf16 hi/lo split ====================
__global__ __launch_bounds__(256)
void ln_split(const float* __restrict__ x, const float* __restrict__ g,
              const float* __restrict__ b, __nv_bfloat16* __restrict__ oh,
              __nv_bfloat16* __restrict__ ol) {
    int row = blockIdx.x;
    int tid = threadIdx.x;
    float4 v4 = ((const float4*)(x + (size_t)row * D))[tid];
    float s  = v4.x + v4.y + v4.z + v4.w;
    float ss = v4.x*v4.x + v4.y*v4.y + v4.z*v4.z + v4.w*v4.w;
    #pragma unroll
    for (int off = 16; off; off >>= 1) {
        s  += __shfl_xor_sync(0xffffffffu, s,  off);
        ss += __shfl_xor_sync(0xffffffffu, ss, off);
    }
    __shared__ float rs[8], rss[8];
    int warp = tid >> 5, lane = tid & 31;
    if (lane == 0) { rs[warp] = s; rss[warp] = ss; }
    __syncthreads();
    float tot = 0.f, tot2 = 0.f;
    #pragma unroll
    for (int i = 0; i < 8; i++) { tot += rs[i]; tot2 += rss[i]; }
    float mu = tot * (1.0f / D);
    float rstd = rsqrtf(tot2 * (1.0f / D) - mu * mu + 1e-5f);
    float4 g4 = ((const float4*)g)[tid];
    float4 b4 = ((const float4*)b)[tid];
    float o[4];
    o[0] = (v4.x - mu) * rstd * g4.x + b4.x;
    o[1] = (v4.y - mu) * rstd * g4.y + b4.y;
    o[2] = (v4.z - mu) * rstd * g4.z + b4.z;
    o[3] = (v4.w - mu) * rstd * g4.w + b4.w;
    size_t base = (size_t)row * D + tid * 4;
    #pragma unroll
    for (int j = 0; j < 4; j += 2) {
        __nv_bfloat16 h0 = __float2bfloat16(o[j]);
        __nv_bfloat16 h1 = __float2bfloat16(o[j+1]);
        __nv_bfloat16 l0 = __float2bfloat16(o[j]   - __bfloat162float(h0));
        __nv_bfloat16 l1 = __float2bfloat16(o[j+1] - __bfloat162float(h1));
        *(__nv_bfloat162*)(oh + base + j) = __nv_bfloat162(h0, h1);
        *(__nv_bfloat162*)(ol + base + j) = __nv_bfloat162(l0, l1);
    }
}

// ================= HMMA bf16x3 GEMM =========================================
// C[M,N] = A[M,K] @ W[K,N] with A,W given as bf16 hi/lo splits.
// CTA 128x128, K-chunk 32, 3-stage cp.async pipeline, 8 warps (64x32 each).
// EPI: 0 = store fp32; 1 = +bias+res -> fp32; 2 = relu(+bias) -> bf16 hi/lo.
#define STAGES 3
#define AH_OFF 0
#define AL_OFF 10240
#define BH_OFF 20480
#define BL_OFF 28672
#define STG    36864
#define GEMM_SMEM (STAGES * STG)

template<int EPI>
__global__ __launch_bounds__(256, 1)
void gemm_tc(const __nv_bfloat16* __restrict__ Ah, const __nv_bfloat16* __restrict__ Al,
             const __nv_bfloat16* __restrict__ Wh, const __nv_bfloat16* __restrict__ Wl,
             const float* __restrict__ bias, const float* __restrict__ res,
             float* __restrict__ Cf, __nv_bfloat16* __restrict__ Ch,
             __nv_bfloat16* __restrict__ Cl, int M, int N, int K) {
    extern __shared__ char smem[];
    uint32_t sbase = smem_u32(smem);
    const int tid = threadIdx.x;
    const int lane = tid & 31, wid = tid >> 5;
    const int wr = wid >> 2, wc = wid & 3;   // warp tile: rows wr*64, cols wc*32
    const int m0 = blockIdx.y * 128, n0 = blockIdx.x * 128;
    const int nch = K >> 5;

    float acc[4][4][4];
    #pragma unroll
    for (int i = 0; i < 4; i++)
        #pragma unroll
        for (int j = 0; j < 4; j++)
            #pragma unroll
            for (int q = 0; q < 4; q++) acc[i][j][q] = 0.f;

    // ---- async stage loader ----
    auto load_stage = [&](int st, int c) {
        uint32_t sb = sbase + st * STG;
        int k0 = c << 5;
        #pragma unroll
        for (int i = 0; i < 2; i++) {         // A: 128 rows x 4 16B-chunks
            int pos = i * 256 + tid;
            int row = pos >> 2, kc = pos & 3;
            uint32_t so = row * 80 + kc * 16;
            const __nv_bfloat16* gh = Ah + (size_t)(m0 + row) * K + k0 + kc * 8;
            const __nv_bfloat16* gl = Al + (size_t)(m0 + row) * K + k0 + kc * 8;
            cp16(sb + AH_OFF + so, gh);
            cp16(sb + AL_OFF + so, gl);
        }
        #pragma unroll
        for (int i = 0; i < 2; i++) {         // B: 32 k-rows x 16 16B-chunks (swizzled)
            int pos = i * 256 + tid;
            int krow = pos >> 4, cch = pos & 15;
            uint32_t so = krow * 256 + ((cch ^ (krow & 7)) * 16);
            const __nv_bfloat16* gh = Wh + (size_t)(k0 + krow) * N + n0 + cch * 8;
            const __nv_bfloat16* gl = Wl + (size_t)(k0 + krow) * N + n0 + cch * 8;
            cp16(sb + BH_OFF + so, gh);
            cp16(sb + BL_OFF + so, gl);
        }
    };

    // prologue: stages 0..S-2
    #pragma unroll
    for (int s = 0; s < STAGES - 1; s++) { load_stage(s, s); CP_COMMIT(); }

    for (int c = 0; c < nch; c++) {
        if (c + STAGES - 1 < nch) load_stage((c + STAGES - 1) % STAGES, c + STAGES - 1);
        CP_COMMIT();
        CP_WAIT(STAGES - 1);
        __syncthreads();

        uint32_t sb = sbase + (c % STAGES) * STG;
        #pragma unroll
        for (int ks = 0; ks < 2; ks++) {
            uint32_t ah[4][4], al[4][4], bh[4][2], bl[4][2];
            #pragma unroll
            for (int fm = 0; fm < 4; fm++) {
                int mloc = wr * 64 + fm * 16 + (lane & 15);
                uint32_t byte = mloc * 80 + ks * 32 + ((lane >> 4) & 1) * 16;
                ldsm_x4(ah[fm], sb + AH_OFF + byte);
                ldsm_x4(al[fm], sb + AL_OFF + byte);
            }
            #pragma unroll
            for (int fn = 0; fn < 4; fn++) {
                int kloc = ks * 16 + (lane & 15);
                int cch = wc * 4 + fn;
                uint32_t byte = kloc * 256 + ((cch ^ (kloc & 7)) * 16);
                ldsm_x2t(bh[fn], sb + BH_OFF + byte);
                ldsm_x2t(bl[fn], sb + BL_OFF + byte);
            }
            #pragma unroll
            for (int fm = 0; fm < 4; fm++)
                #pragma unroll
                for (int fn = 0; fn < 4; fn++) {
                    mma_bf16(acc[fm][fn], ah[fm], bh[fn]);
                    mma_bf16(acc[fm][fn], ah[fm], bl[fn]);
                    mma_bf16(acc[fm][fn], al[fm], bh[fn]);
                }
        }
        __syncthreads();
    }

    // ---- epilogue ----
    int grp = lane >> 2, tg = lane & 3;
    #pragma unroll
    for (int fm = 0; fm < 4; fm++) {
        int r0 = m0 + wr * 64 + fm * 16 + grp;
        #pragma unroll
        for (int fn = 0; fn < 4; fn++) {
            int c0 = n0 + wc * 32 + fn * 8 + tg * 2;
            float* dd = acc[fm][fn];
            #pragma unroll
            for (int half = 0; half < 2; half++) {
                int r = r0 + half * 8;
                float v0 = dd[half * 2 + 0], v1 = dd[half * 2 + 1];
                if (EPI == 0) {
                    float2* p = (float2*)(Cf + (size_t)r * N + c0);
                    *p = make_float2(v0, v1);
                } else if (EPI == 1) {
                    const float2 rv = *(const float2*)(res + (size_t)r * N + c0);
                    const float2 bv = *(const float2*)(bias + c0);
                    float2* p = (float2*)(Cf + (size_t)r * N + c0);
                    *p = make_float2(v0 + bv.x + rv.x, v1 + bv.y + rv.y);
                } else {
                    const float2 bv = *(const float2*)(bias + c0);
                    float a0 = fmaxf(v0 + bv.x, 0.f), a1 = fmaxf(v1 + bv.y, 0.f);
                    __nv_bfloat16 h0 = __float2bfloat16(a0);
                    __nv_bfloat16 h1 = __float2bfloat16(a1);
                    __nv_bfloat16 l0 = __float2bfloat16(a0 - __bfloat162float(h0));
                    __nv_bfloat16 l1 = __float2bfloat16(a1 - __bfloat162float(h1));
                    *(__nv_bfloat162*)(Ch + (size_t)r * N + c0) = __nv_bfloat162(h0, h1);
                    *(__nv_bfloat162*)(Cl + (size_t)r * N + c0) = __nv_bfloat162(l0, l1);
                }
            }
        }
    }
}

// ================= flash attention fp32, 128x128, FFMA exp ==================
__device__ __forceinline__ float fexp(float x) {
    float y = fmaxf(x * 1.4426950408889634f, -126.0f);
    float n = rintf(y);
    float t = (y - n) * 0.6931471805599453f;   // |t| <= 0.347
    float p = fmaf(t, 8.3333333e-3f, 4.1666667e-2f);
    p = fmaf(p, t, 0.166666667f);
    p = fmaf(p, t, 0.5f);
    p = fmaf(p, t, 1.0f);
    p = fmaf(p, t, 1.0f);
    return __int_as_float(((int)n + 127) << 23) * p;
}

#define FP_Q  65
#define FP_KT 132
#define FP_V  68
#define FP_S  132
#define FLASH_SMEM ((128*FP_Q + 64*FP_KT + 128*FP_V + 128*FP_S) * 4)

__global__ __launch_bounds__(256, 1)
void flash_kernel(const float* __restrict__ qkv,
                  __nv_bfloat16* __restrict__ oh, __nv_bfloat16* __restrict__ ol) {
    extern __shared__ float fsm[];
    float* Qs  = fsm;                 // [128][65]
    float* KsT = Qs + 128 * FP_Q;     // [64][132]  (hs-major)
    float* Vs  = KsT + 64 * FP_KT;    // [128][68]
    float* Ss  = Vs + 128 * FP_V;     // [128][132]

    int qt = blockIdx.x, h = blockIdx.y, b = blockIdx.z;
    int q0 = qt * 128;
    int tid = threadIdx.x;
    int ty = tid >> 4, tx = tid & 15;
    const size_t rowstride = 3 * D;   // 3072
    const float* qb = qkv + (size_t)h * HS;
    const float* kb = qkv + D + (size_t)h * HS;
    const float* vb = qkv + 2 * D + (size_t)h * HS;

    // load Q tile (128 x 64)
    #pragma unroll
    for (int it = 0; it < 8; it++) {
        int idx = tid + it * 256;     // 0..2047
        int row = idx >> 4, c4 = (idx & 15) * 4;
        float4 qv = *(const float4*)(qb + (size_t)(b * T + q0 + row) * rowstride + c4);
        Qs[row * FP_Q + c4 + 0] = qv.x; Qs[row * FP_Q + c4 + 1] = qv.y;
        Qs[row * FP_Q + c4 + 2] = qv.z; Qs[row * FP_Q + c4 + 3] = qv.w;
    }

    float m_i[8], l_i[8], acc[8][4];
    #pragma unroll
    for (int i = 0; i < 8; i++) {
        m_i[i] = -1e30f; l_i[i] = 0.f;
        #pragma unroll
        for (int j = 0; j < 4; j++) acc[i][j] = 0.f;
    }
    const float scale = 0.03125f;     // 1024^-0.5

    for (int kt = 0; kt <= qt; kt++) {
        int k0 = kt * 128;
        __syncthreads();              // prev iter done reading Vs/Ss (+ Q store iter 0)
        #pragma unroll
        for (int it = 0; it < 8; it++) {
            int idx = tid + it * 256;
            int row = idx >> 4, c4 = (idx & 15) * 4;
            size_t goff = (size_t)(b * T + k0 + row) * rowstride + c4;
            float4 kv = *(const float4*)(kb + goff);
            float4 vv = *(const float4*)(vb + goff);
            KsT[(c4 + 0) * FP_KT + row] = kv.x;
            KsT[(c4 + 1) * FP_KT + row] = kv.y;
            KsT[(c4 + 2) * FP_KT + row] = kv.z;
            KsT[(c4 + 3) * FP_KT + row] = kv.w;
            *(float4*)(Vs + row * FP_V + c4) = vv;
        }
        __syncthreads();

        // S = scale * Q K^T : 8x8 fragment
        float s[8][8];
        #pragma unroll
        for (int i = 0; i < 8; i++)
            #pragma unroll
            for (int j = 0; j < 8; j++) s[i][j] = 0.f;
        #pragma unroll 4
        for (int kk = 0; kk < 64; kk++) {
            float a[8], bb[8];
            #pragma unroll
            for (int i = 0; i < 8; i++) a[i] = Qs[(ty * 8 + i) * FP_Q + kk];
            *(float4*)(bb)     = *(const float4*)(KsT + kk * FP_KT + tx * 8);
            *(float4*)(bb + 4) = *(const float4*)(KsT + kk * FP_KT + tx * 8 + 4);
            #pragma unroll
            for (int i = 0; i < 8; i++)
                #pragma unroll
                for (int j = 0; j < 8; j++)
                    s[i][j] = fmaf(a[i], bb[j], s[i][j]);
        }
        bool diag = (kt == qt);
        #pragma unroll
        for (int i = 0; i < 8; i++) {
            int qi = q0 + ty * 8 + i;
            #pragma unroll
            for (int j = 0; j < 8; j++) {
                s[i][j] *= scale;
                if (diag && (k0 + tx * 8 + j > qi)) s[i][j] = -1e30f;
            }
        }
        // online softmax (16 threads per row)
        #pragma unroll
        for (int i = 0; i < 8; i++) {
            float rmax = s[i][0];
            #pragma unroll
            for (int j = 1; j < 8; j++) rmax = fmaxf(rmax, s[i][j]);
            #pragma unroll
            for (int off = 1; off < 16; off <<= 1)
                rmax = fmaxf(rmax, __shfl_xor_sync(0xffffffffu, rmax, off));
            float m_new = fmaxf(m_i[i], rmax);
            float alpha = fexp(m_i[i] - m_new);
            float rsum = 0.f, p[8];
            #pragma unroll
            for (int j = 0; j < 8; j++) { p[j] = fexp(s[i][j] - m_new); rsum += p[j]; }
            #pragma unroll
            for (int off = 1; off < 16; off <<= 1)
                rsum += __shfl_xor_sync(0xffffffffu, rsum, off);
            l_i[i] = l_i[i] * alpha + rsum;
            m_i[i] = m_new;
            #pragma unroll
            for (int j = 0; j < 4; j++) acc[i][j] *= alpha;
            float* srow = Ss + (ty * 8 + i) * FP_S + tx * 8;
            *(float4*)(srow)     = make_float4(p[0], p[1], p[2], p[3]);
            *(float4*)(srow + 4) = make_float4(p[4], p[5], p[6], p[7]);
        }
        __syncthreads();
        // O += P @ V : 8x4 fragment
        #pragma unroll 4
        for (int kk = 0; kk < 128; kk++) {
            float a[8];
            #pragma unroll
            for (int i = 0; i < 8; i++) a[i] = Ss[(ty * 8 + i) * FP_S + kk];
            float4 vv = *(const float4*)(Vs + kk * FP_V + tx * 4);
            #pragma unroll
            for (int i = 0; i < 8; i++) {
                acc[i][0] = fmaf(a[i], vv.x, acc[i][0]);
                acc[i][1] = fmaf(a[i], vv.y, acc[i][1]);
                acc[i][2] = fmaf(a[i], vv.z, acc[i][2]);
                acc[i][3] = fmaf(a[i], vv.w, acc[i][3]);
            }
        }
    }
    // epilogue: normalize + bf16 hi/lo split to [b,t,h*hs]
    #pragma unroll
    for (int i = 0; i < 8; i++) {
        float inv = 1.0f / l_i[i];
        size_t base = (size_t)(b * T + q0 + ty * 8 + i) * D + h * HS + tx * 4;
        #pragma unroll
        for (int j = 0; j < 4; j += 2) {
            float v0 = acc[i][j] * inv, v1 = acc[i][j+1] * inv;
            __nv_bfloat16 h0 = __float2bfloat16(v0);
            __nv_bfloat16 h1 = __float2bfloat16(v1);
            __nv_bfloat16 l0 = __float2bfloat16(v0 - __bfloat162float(h0));
            __nv_bfloat16 l1 = __float2bfloat16(v1 - __bfloat162float(h1));
            *(__nv_bfloat162*)(oh + base + j) = __nv_bfloat162(h0, h1);
            *(__nv_bfloat162*)(ol + base + j) = __nv_bfloat162(l0, l1);
        }
    }
}

// ================= launch ===================================================
extern "C" void kernel_launch(void* const* d_in, const int* in_sizes, int n_in,
                              void* d_out, int out_size) {
    const float* x   = (const float*)d_in[0];
    const float* wq  = (const float*)d_in[1];
    const float* wk  = (const float*)d_in[2];
    const float* wv  = (const float*)d_in[3];
    const float* wo  = (const float*)d_in[4];
    const float* bo  = (const float*)d_in[5];
    const float* w1  = (const float*)d_in[6];
    const float* b1  = (const float*)d_in[7];
    const float* w2  = (const float*)d_in[8];
    const float* b2  = (const float*)d_in[9];
    const float* g1  = (const float*)d_in[10];
    const float* be1 = (const float*)d_in[11];
    const float* g2  = (const float*)d_in[12];
    const float* be2 = (const float*)d_in[13];
    float* out = (float*)d_out;

    __nv_bfloat16 *xnh, *xnl, *wqkvh, *wqkvl, *woh, *wol, *w1h, *w1l, *w2h, *w2l, *h1h, *h1l;
    float *qkv, *x1;
    cudaGetSymbolAddress((void**)&xnh, g_xnh);     cudaGetSymbolAddress((void**)&xnl, g_xnl);
    cudaGetSymbolAddress((void**)&wqkvh, g_wqkvh); cudaGetSymbolAddress((void**)&wqkvl, g_wqkvl);
    cudaGetSymbolAddress((void**)&woh, g_woh);     cudaGetSymbolAddress((void**)&wol, g_wol);
    cudaGetSymbolAddress((void**)&w1h, g_w1h);     cudaGetSymbolAddress((void**)&w1l, g_w1l);
    cudaGetSymbolAddress((void**)&w2h, g_w2h);     cudaGetSymbolAddress((void**)&w2l, g_w2l);
    cudaGetSymbolAddress((void**)&h1h, g_h1h);     cudaGetSymbolAddress((void**)&h1l, g_h1l);
    cudaGetSymbolAddress((void**)&qkv, g_qkv);     cudaGetSymbolAddress((void**)&x1, g_x1);

    static bool attr_done = false;
    if (!attr_done) {
        cudaFuncSetAttribute(gemm_tc<0>, cudaFuncAttributeMaxDynamicSharedMemorySize, GEMM_SMEM);
        cudaFuncSetAttribute(gemm_tc<1>, cudaFuncAttributeMaxDynamicSharedMemorySize, GEMM_SMEM);
        cudaFuncSetAttribute(gemm_tc<2>, cudaFuncAttributeMaxDynamicSharedMemorySize, GEMM_SMEM);
        cudaFuncSetAttribute(flash_kernel, cudaFuncAttributeMaxDynamicSharedMemorySize, FLASH_SMEM);
        attr_done = true;
    }

    // weight splits (no transpose; QKV fused into [1024][3072])
    wsplit<<<1024, 256>>>(wq, wqkvh, wqkvl, D, 3 * D, 0);
    wsplit<<<1024, 256>>>(wk, wqkvh, wqkvl, D, 3 * D, D);
    wsplit<<<1024, 256>>>(wv, wqkvh, wqkvl, D, 3 * D, 2 * D);
    wsplit<<<1024, 256>>>(wo, woh, wol, D, D, 0);
    wsplit<<<4096, 256>>>(w1, w1h, w1l, D4, D4, 0);
    wsplit<<<4096, 256>>>(w2, w2h, w2l, D, D, 0);

    // LN1 (split output)
    ln_split<<<BT, 256>>>(x, g1, be1, xnh, xnl);

    // fused QKV: [8192,1024] @ [1024,3072] -> qkv fp32
    gemm_tc<0><<<dim3(3 * D / 128, BT / 128), 256, GEMM_SMEM>>>(
        xnh, xnl, wqkvh, wqkvl, nullptr, nullptr, qkv, nullptr, nullptr, BT, 3 * D, D);

    // flash attention -> attn split into xnh/xnl
    flash_kernel<<<dim3(T / 128, H, Bsz), 256, FLASH_SMEM>>>(qkv, xnh, xnl);

    // Wo + bo + residual(x) -> x1
    gemm_tc<1><<<dim3(D / 128, BT / 128), 256, GEMM_SMEM>>>(
        xnh, xnl, woh, wol, bo, x, x1, nullptr, nullptr, BT, D, D);

    // LN2 -> xn split (reused)
    ln_split<<<BT, 256>>>(x1, g2, be2, xnh, xnl);

    // FFN up: relu(xn @ w1 + b1) -> h1 split
    gemm_tc<2><<<dim3(D4 / 128, BT / 128), 256, GEMM_SMEM>>>(
        xnh, xnl, w1h, w1l, b1, nullptr, nullptr, h1h, h1l, BT, D4, D);

    // FFN down: h1 @ w2 + b2 + residual(x1) -> out
    gemm_tc<1><<<dim3(D / 128, BT / 128), 256, GEMM_SMEM>>>(
        h1h, h1l, w2h, w2l, b2, x1, out, nullptr, nullptr, BT, D, D4);
}

// round 4
// speedup vs baseline: 2.3315x; 1.0852x over previous
#include <cuda_runtime.h>
#include <cuda_bf16.h>
#include <cstdint>
#include <math.h>

#define Bsz 4
#define T   2048
#define D   1024
#define H   16
#define HS  64
#define BT  (Bsz*T)      // 8192
#define D4  (4*D)        // 4096

// ======================= scratch ============================================
__device__ __nv_bfloat16 g_xnh[BT*D], g_xnl[BT*D];        // LN out / attn out (reused)
__device__ __nv_bfloat16 g_wqkvh[(size_t)D*3*D], g_wqkvl[(size_t)D*3*D]; // [1024][3072]
__device__ __nv_bfloat16 g_woh[D*D], g_wol[D*D];          // [1024][1024]
__device__ __nv_bfloat16 g_w1h[(size_t)D*D4], g_w1l[(size_t)D*D4];  // [1024][4096]
__device__ __nv_bfloat16 g_w2h[(size_t)D4*D], g_w2l[(size_t)D4*D];  // [4096][1024]
__device__ float g_qkv[(size_t)BT*3*D];                   // fused qkv fp32 [8192][3072]
__device__ __nv_bfloat16 g_h1h[(size_t)BT*D4], g_h1l[(size_t)BT*D4];
__device__ float g_x1[BT*D];

// ======================= small asm helpers ==================================
__device__ __forceinline__ uint32_t smem_u32(const void* p) {
    uint32_t a;
    asm("{ .reg .u64 t; cvta.to.shared.u64 t, %1; cvt.u32.u64 %0, t; }"
        : "=r"(a) : "l"(p));
    return a;
}
__device__ __forceinline__ void cp16(uint32_t s, const void* g) {
    asm volatile("cp.async.cg.shared.global [%0], [%1], 16;" :: "r"(s), "l"(g));
}
#define CP_COMMIT() asm volatile("cp.async.commit_group;" ::: "memory")
#define CP_WAIT(n)  asm volatile("cp.async.wait_group %0;" :: "n"(n) : "memory")

__device__ __forceinline__ void ldsm_x4(uint32_t* r, uint32_t a) {
    asm volatile("ldmatrix.sync.aligned.m8n8.x4.shared.b16 {%0,%1,%2,%3}, [%4];"
                 : "=r"(r[0]), "=r"(r[1]), "=r"(r[2]), "=r"(r[3]) : "r"(a));
}
__device__ __forceinline__ void ldsm_x2t(uint32_t* r, uint32_t a) {
    asm volatile("ldmatrix.sync.aligned.m8n8.x2.trans.shared.b16 {%0,%1}, [%2];"
                 : "=r"(r[0]), "=r"(r[1]) : "r"(a));
}
__device__ __forceinline__ void mma_bf16(float* d, const uint32_t* a, const uint32_t* b) {
    asm volatile(
        "mma.sync.aligned.m16n8k16.row.col.f32.bf16.bf16.f32 "
        "{%0,%1,%2,%3}, {%4,%5,%6,%7}, {%8,%9}, {%0,%1,%2,%3};"
        : "+f"(d[0]), "+f"(d[1]), "+f"(d[2]), "+f"(d[3])
        : "r"(a[0]), "r"(a[1]), "r"(a[2]), "r"(a[3]), "r"(b[0]), "r"(b[1]));
}

// ================= weight bf16 hi/lo split (no transpose) ===================
__global__ __launch_bounds__(256)
void wsplit(const float* __restrict__ W, __nv_bfloat16* __restrict__ Th,
            __nv_bfloat16* __restrict__ Tl, int n_src, int dst_stride, int col_off) {
    size_t p4 = ((size_t)blockIdx.x * 256 + threadIdx.x) * 4;
    float4 w = *(const float4*)(W + p4);
    int k = (int)(p4 / n_src), n = (int)(p4 % n_src);
    size_t o = (size_t)k * dst_stride + col_off + n;
    float vv[4] = {w.x, w.y, w.z, w.w};
    #pragma unroll
    for (int j = 0; j < 4; j += 2) {
        __nv_bfloat16 h0 = __float2bfloat16(vv[j]);
        __nv_bfloat16 h1 = __float2bfloat16(vv[j+1]);
        __nv_bfloat16 l0 = __float2bfloat16(vv[j]   - __bfloat162float(h0));
        __nv_bfloat16 l1 = __float2bfloat16(vv[j+1] - __bfloat162float(h1));
        *(__nv_bfloat162*)(Th + o + j) = __nv_bfloat162(h0, h1);
        *(__nv_bfloat162*)(Tl + o + j) = __nv_bfloat162(l0, l1);
    }
}

// ================= LayerNorm with fused bf16 hi/lo split ====================
__global__ __launch_bounds__(256)
void ln_split(const float* __restrict__ x, const float* __restrict__ g,
              const float* __restrict__ b, __nv_bfloat16* __restrict__ oh,
              __nv_bfloat16* __restrict__ ol) {
    int row = blockIdx.x;
    int tid = threadIdx.x;
    float4 v4 = ((const float4*)(x + (size_t)row * D))[tid];
    float s  = v4.x + v4.y + v4.z + v4.w;
    float ss = v4.x*v4.x + v4.y*v4.y + v4.z*v4.z + v4.w*v4.w;
    #pragma unroll
    for (int off = 16; off; off >>= 1) {
        s  += __shfl_xor_sync(0xffffffffu, s,  off);
        ss += __shfl_xor_sync(0xffffffffu, ss, off);
    }
    __shared__ float rs[8], rss[8];
    int warp = tid >> 5, lane = tid & 31;
    if (lane == 0) { rs[warp] = s; rss[warp] = ss; }
    __syncthreads();
    float tot = 0.f, tot2 = 0.f;
    #pragma unroll
    for (int i = 0; i < 8; i++) { tot += rs[i]; tot2 += rss[i]; }
    float mu = tot * (1.0f / D);
    float rstd = rsqrtf(tot2 * (1.0f / D) - mu * mu + 1e-5f);
    float4 g4 = ((const float4*)g)[tid];
    float4 b4 = ((const float4*)b)[tid];
    float o[4];
    o[0] = (v4.x - mu) * rstd * g4.x + b4.x;
    o[1] = (v4.y - mu) * rstd * g4.y + b4.y;
    o[2] = (v4.z - mu) * rstd * g4.z + b4.z;
    o[3] = (v4.w - mu) * rstd * g4.w + b4.w;
    size_t base = (size_t)row * D + tid * 4;
    #pragma unroll
    for (int j = 0; j < 4; j += 2) {
        __nv_bfloat16 h0 = __float2bfloat16(o[j]);
        __nv_bfloat16 h1 = __float2bfloat16(o[j+1]);
        __nv_bfloat16 l0 = __float2bfloat16(o[j]   - __bfloat162float(h0));
        __nv_bfloat16 l1 = __float2bfloat16(o[j+1] - __bfloat162float(h1));
        *(__nv_bfloat162*)(oh + base + j) = __nv_bfloat162(h0, h1);
        *(__nv_bfloat162*)(ol + base + j) = __nv_bfloat162(l0, l1);
    }
}

// ================= HMMA bf16x3 GEMM =========================================
// C[M,N] = A[M,K] @ W[K,N], A/W as bf16 hi/lo splits.
// CTA 128x256, K-chunk 32, 3-stage cp.async pipeline, 8 warps = 2x4 of 64x64.
// EPI: 0 = store fp32; 1 = +bias+res -> fp32; 2 = relu(+bias) -> bf16 hi/lo.
#define STAGES 3
#define AH_OFF 0
#define AL_OFF 10240
#define BH_OFF 20480
#define BL_OFF 36864
#define STG    53248
#define GEMM_SMEM (STAGES * STG)

template<int EPI>
__global__ __launch_bounds__(256, 1)
void gemm_tc(const __nv_bfloat16* __restrict__ Ah, const __nv_bfloat16* __restrict__ Al,
             const __nv_bfloat16* __restrict__ Wh, const __nv_bfloat16* __restrict__ Wl,
             const float* __restrict__ bias, const float* __restrict__ res,
             float* __restrict__ Cf, __nv_bfloat16* __restrict__ Ch,
             __nv_bfloat16* __restrict__ Cl, int M, int N, int K) {
    extern __shared__ char smem[];
    uint32_t sbase = smem_u32(smem);
    const int tid = threadIdx.x;
    const int lane = tid & 31, wid = tid >> 5;
    const int wr = wid >> 2, wc = wid & 3;   // warp tile: rows wr*64, cols wc*64
    const int m0 = blockIdx.y * 128, n0 = blockIdx.x * 256;
    const int nch = K >> 5;

    float acc[4][8][4];
    #pragma unroll
    for (int i = 0; i < 4; i++)
        #pragma unroll
        for (int j = 0; j < 8; j++)
            #pragma unroll
            for (int q = 0; q < 4; q++) acc[i][j][q] = 0.f;

    // ---- async stage loader ----
    auto load_stage = [&](int st, int c) {
        uint32_t sb = sbase + st * STG;
        int k0 = c << 5;
        #pragma unroll
        for (int i = 0; i < 2; i++) {         // A: 128 rows x 4 16B-chunks (hi+lo)
            int pos = i * 256 + tid;
            int row = pos >> 2, kc = pos & 3;
            uint32_t so = row * 80 + kc * 16;
            cp16(sb + AH_OFF + so, Ah + (size_t)(m0 + row) * K + k0 + kc * 8);
            cp16(sb + AL_OFF + so, Al + (size_t)(m0 + row) * K + k0 + kc * 8);
        }
        #pragma unroll
        for (int i = 0; i < 4; i++) {         // B: 32 k-rows x 32 16B-chunks (swizzled)
            int pos = i * 256 + tid;
            int krow = pos >> 5, cch = pos & 31;
            uint32_t so = krow * 512 + ((cch ^ (krow & 7)) * 16);
            cp16(sb + BH_OFF + so, Wh + (size_t)(k0 + krow) * N + n0 + cch * 8);
            cp16(sb + BL_OFF + so, Wl + (size_t)(k0 + krow) * N + n0 + cch * 8);
        }
    };

    // prologue: stages 0..S-2
    #pragma unroll
    for (int s = 0; s < STAGES - 1; s++) { load_stage(s, s); CP_COMMIT(); }

    for (int c = 0; c < nch; c++) {
        if (c + STAGES - 1 < nch) load_stage((c + STAGES - 1) % STAGES, c + STAGES - 1);
        CP_COMMIT();
        CP_WAIT(STAGES - 1);
        __syncthreads();

        uint32_t sb = sbase + (c % STAGES) * STG;
        #pragma unroll
        for (int ks = 0; ks < 2; ks++) {
            // B fragments for this warp's 64 cols (8 n8-frags, hi+lo)
            uint32_t bh[8][2], bl[8][2];
            int kloc = ks * 16 + (lane & 15);
            #pragma unroll
            for (int fn = 0; fn < 8; fn++) {
                int cch = wc * 8 + fn;
                uint32_t byte = kloc * 512 + ((cch ^ (kloc & 7)) * 16);
                ldsm_x2t(bh[fn], sb + BH_OFF + byte);
                ldsm_x2t(bl[fn], sb + BL_OFF + byte);
            }
            #pragma unroll
            for (int fm = 0; fm < 4; fm++) {
                uint32_t ah[4], al[4];
                int mloc = wr * 64 + fm * 16 + (lane & 15);
                uint32_t byte = mloc * 80 + ks * 32 + ((lane >> 4) & 1) * 16;
                ldsm_x4(ah, sb + AH_OFF + byte);
                ldsm_x4(al, sb + AL_OFF + byte);
                #pragma unroll
                for (int fn = 0; fn < 8; fn++) {
                    mma_bf16(acc[fm][fn], ah, bh[fn]);
                    mma_bf16(acc[fm][fn], ah, bl[fn]);
                    mma_bf16(acc[fm][fn], al, bh[fn]);
                }
            }
        }
        __syncthreads();
    }

    // ---- epilogue ----
    int grp = lane >> 2, tg = lane & 3;
    #pragma unroll
    for (int fm = 0; fm < 4; fm++) {
        int r0 = m0 + wr * 64 + fm * 16 + grp;
        #pragma unroll
        for (int fn = 0; fn < 8; fn++) {
            int c0 = n0 + wc * 64 + fn * 8 + tg * 2;
            float* dd = acc[fm][fn];
            #pragma unroll
            for (int half = 0; half < 2; half++) {
                int r = r0 + half * 8;
                float v0 = dd[half * 2 + 0], v1 = dd[half * 2 + 1];
                if (EPI == 0) {
                    *(float2*)(Cf + (size_t)r * N + c0) = make_float2(v0, v1);
                } else if (EPI == 1) {
                    const float2 rv = *(const float2*)(res + (size_t)r * N + c0);
                    const float2 bv = *(const float2*)(bias + c0);
                    *(float2*)(Cf + (size_t)r * N + c0) =
                        make_float2(v0 + bv.x + rv.x, v1 + bv.y + rv.y);
                } else {
                    const float2 bv = *(const float2*)(bias + c0);
                    float a0 = fmaxf(v0 + bv.x, 0.f), a1 = fmaxf(v1 + bv.y, 0.f);
                    __nv_bfloat16 h0 = __float2bfloat16(a0);
                    __nv_bfloat16 h1 = __float2bfloat16(a1);
                    __nv_bfloat16 l0 = __float2bfloat16(a0 - __bfloat162float(h0));
                    __nv_bfloat16 l1 = __float2bfloat16(a1 - __bfloat162float(h1));
                    *(__nv_bfloat162*)(Ch + (size_t)r * N + c0) = __nv_bfloat162(h0, h1);
                    *(__nv_bfloat162*)(Cl + (size_t)r * N + c0) = __nv_bfloat162(l0, l1);
                }
            }
        }
    }
}

// ================= flash attention fp32, 128x128, FFMA exp ==================
__device__ __forceinline__ float fexp(float x) {
    float y = fmaxf(x * 1.4426950408889634f, -126.0f);
    float n = rintf(y);
    float t = (y - n) * 0.6931471805599453f;   // |t| <= 0.347
    float p = fmaf(t, 8.3333333e-3f, 4.1666667e-2f);
    p = fmaf(p, t, 0.166666667f);
    p = fmaf(p, t, 0.5f);
    p = fmaf(p, t, 1.0f);
    p = fmaf(p, t, 1.0f);
    return __int_as_float(((int)n + 127) << 23) * p;
}

#define FP_Q  65
#define FP_KT 132
#define FP_V  68
#define FP_S  132
#define FLASH_SMEM ((128*FP_Q + 64*FP_KT + 128*FP_V + 128*FP_S) * 4)

__global__ __launch_bounds__(256, 1)
void flash_kernel(const float* __restrict__ qkv,
                  __nv_bfloat16* __restrict__ oh, __nv_bfloat16* __restrict__ ol) {
    extern __shared__ float fsm[];
    float* Qs  = fsm;                 // [128][65]
    float* KsT = Qs + 128 * FP_Q;     // [64][132]  (hs-major)
    float* Vs  = KsT + 64 * FP_KT;    // [128][68]
    float* Ss  = Vs + 128 * FP_V;     // [128][132]

    int qt = blockIdx.x, h = blockIdx.y, b = blockIdx.z;
    int q0 = qt * 128;
    int tid = threadIdx.x;
    int ty = tid >> 4, tx = tid & 15;
    const size_t rowstride = 3 * D;   // 3072
    const float* qb = qkv + (size_t)h * HS;
    const float* kb = qkv + D + (size_t)h * HS;
    const float* vb = qkv + 2 * D + (size_t)h * HS;

    // load Q tile (128 x 64)
    #pragma unroll
    for (int it = 0; it < 8; it++) {
        int idx = tid + it * 256;     // 0..2047
        int row = idx >> 4, c4 = (idx & 15) * 4;
        float4 qv = *(const float4*)(qb + (size_t)(b * T + q0 + row) * rowstride + c4);
        Qs[row * FP_Q + c4 + 0] = qv.x; Qs[row * FP_Q + c4 + 1] = qv.y;
        Qs[row * FP_Q + c4 + 2] = qv.z; Qs[row * FP_Q + c4 + 3] = qv.w;
    }

    float m_i[8], l_i[8], acc[8][4];
    #pragma unroll
    for (int i = 0; i < 8; i++) {
        m_i[i] = -1e30f; l_i[i] = 0.f;
        #pragma unroll
        for (int j = 0; j < 4; j++) acc[i][j] = 0.f;
    }
    const float scale = 0.03125f;     // 1024^-0.5

    for (int kt = 0; kt <= qt; kt++) {
        int k0 = kt * 128;
        __syncthreads();              // prev iter done reading Vs/Ss (+ Q store iter 0)
        #pragma unroll
        for (int it = 0; it < 8; it++) {
            int idx = tid + it * 256;
            int row = idx >> 4, c4 = (idx & 15) * 4;
            size_t goff = (size_t)(b * T + k0 + row) * rowstride + c4;
            float4 kv = *(const float4*)(kb + goff);
            float4 vv = *(const float4*)(vb + goff);
            KsT[(c4 + 0) * FP_KT + row] = kv.x;
            KsT[(c4 + 1) * FP_KT + row] = kv.y;
            KsT[(c4 + 2) * FP_KT + row] = kv.z;
            KsT[(c4 + 3) * FP_KT + row] = kv.w;
            *(float4*)(Vs + row * FP_V + c4) = vv;
        }
        __syncthreads();

        // S = scale * Q K^T : 8x8 fragment
        float s[8][8];
        #pragma unroll
        for (int i = 0; i < 8; i++)
            #pragma unroll
            for (int j = 0; j < 8; j++) s[i][j] = 0.f;
        #pragma unroll 4
        for (int kk = 0; kk < 64; kk++) {
            float a[8], bb[8];
            #pragma unroll
            for (int i = 0; i < 8; i++) a[i] = Qs[(ty * 8 + i) * FP_Q + kk];
            *(float4*)(bb)     = *(const float4*)(KsT + kk * FP_KT + tx * 8);
            *(float4*)(bb + 4) = *(const float4*)(KsT + kk * FP_KT + tx * 8 + 4);
            #pragma unroll
            for (int i = 0; i < 8; i++)
                #pragma unroll
                for (int j = 0; j < 8; j++)
                    s[i][j] = fmaf(a[i], bb[j], s[i][j]);
        }
        bool diag = (kt == qt);
        #pragma unroll
        for (int i = 0; i < 8; i++) {
            int qi = q0 + ty * 8 + i;
            #pragma unroll
            for (int j = 0; j < 8; j++) {
                s[i][j] *= scale;
                if (diag && (k0 + tx * 8 + j > qi)) s[i][j] = -1e30f;
            }
        }
        // online softmax (16 threads per row)
        #pragma unroll
        for (int i = 0; i < 8; i++) {
            float rmax = s[i][0];
            #pragma unroll
            for (int j = 1; j < 8; j++) rmax = fmaxf(rmax, s[i][j]);
            #pragma unroll
            for (int off = 1; off < 16; off <<= 1)
                rmax = fmaxf(rmax, __shfl_xor_sync(0xffffffffu, rmax, off));
            float m_new = fmaxf(m_i[i], rmax);
            float alpha = fexp(m_i[i] - m_new);
            float rsum = 0.f, p[8];
            #pragma unroll
            for (int j = 0; j < 8; j++) { p[j] = fexp(s[i][j] - m_new); rsum += p[j]; }
            #pragma unroll
            for (int off = 1; off < 16; off <<= 1)
                rsum += __shfl_xor_sync(0xffffffffu, rsum, off);
            l_i[i] = l_i[i] * alpha + rsum;
            m_i[i] = m_new;
            #pragma unroll
            for (int j = 0; j < 4; j++) acc[i][j] *= alpha;
            float* srow = Ss + (ty * 8 + i) * FP_S + tx * 8;
            *(float4*)(srow)     = make_float4(p[0], p[1], p[2], p[3]);
            *(float4*)(srow + 4) = make_float4(p[4], p[5], p[6], p[7]);
        }
        __syncthreads();
        // O += P @ V : 8x4 fragment
        #pragma unroll 4
        for (int kk = 0; kk < 128; kk++) {
            float a[8];
            #pragma unroll
            for (int i = 0; i < 8; i++) a[i] = Ss[(ty * 8 + i) * FP_S + kk];
            float4 vv = *(const float4*)(Vs + kk * FP_V + tx * 4);
            #pragma unroll
            for (int i = 0; i < 8; i++) {
                acc[i][0] = fmaf(a[i], vv.x, acc[i][0]);
                acc[i][1] = fmaf(a[i], vv.y, acc[i][1]);
                acc[i][2] = fmaf(a[i], vv.z, acc[i][2]);
                acc[i][3] = fmaf(a[i], vv.w, acc[i][3]);
            }
        }
    }
    // epilogue: normalize + bf16 hi/lo split to [b,t,h*hs]
    #pragma unroll
    for (int i = 0; i < 8; i++) {
        float inv = 1.0f / l_i[i];
        size_t base = (size_t)(b * T + q0 + ty * 8 + i) * D + h * HS + tx * 4;
        #pragma unroll
        for (int j = 0; j < 4; j += 2) {
            float v0 = acc[i][j] * inv, v1 = acc[i][j+1] * inv;
            __nv_bfloat16 h0 = __float2bfloat16(v0);
            __nv_bfloat16 h1 = __float2bfloat16(v1);
            __nv_bfloat16 l0 = __float2bfloat16(v0 - __bfloat162float(h0));
            __nv_bfloat16 l1 = __float2bfloat16(v1 - __bfloat162float(h1));
            *(__nv_bfloat162*)(oh + base + j) = __nv_bfloat162(h0, h1);
            *(__nv_bfloat162*)(ol + base + j) = __nv_bfloat162(l0, l1);
        }
    }
}

// ================= launch ===================================================
extern "C" void kernel_launch(void* const* d_in, const int* in_sizes, int n_in,
                              void* d_out, int out_size) {
    const float* x   = (const float*)d_in[0];
    const float* wq  = (const float*)d_in[1];
    const float* wk  = (const float*)d_in[2];
    const float* wv  = (const float*)d_in[3];
    const float* wo  = (const float*)d_in[4];
    const float* bo  = (const float*)d_in[5];
    const float* w1  = (const float*)d_in[6];
    const float* b1  = (const float*)d_in[7];
    const float* w2  = (const float*)d_in[8];
    const float* b2  = (const float*)d_in[9];
    const float* g1  = (const float*)d_in[10];
    const float* be1 = (const float*)d_in[11];
    const float* g2  = (const float*)d_in[12];
    const float* be2 = (const float*)d_in[13];
    float* out = (float*)d_out;

    __nv_bfloat16 *xnh, *xnl, *wqkvh, *wqkvl, *woh, *wol, *w1h, *w1l, *w2h, *w2l, *h1h, *h1l;
    float *qkv, *x1;
    cudaGetSymbolAddress((void**)&xnh, g_xnh);     cudaGetSymbolAddress((void**)&xnl, g_xnl);
    cudaGetSymbolAddress((void**)&wqkvh, g_wqkvh); cudaGetSymbolAddress((void**)&wqkvl, g_wqkvl);
    cudaGetSymbolAddress((void**)&woh, g_woh);     cudaGetSymbolAddress((void**)&wol, g_wol);
    cudaGetSymbolAddress((void**)&w1h, g_w1h);     cudaGetSymbolAddress((void**)&w1l, g_w1l);
    cudaGetSymbolAddress((void**)&w2h, g_w2h);     cudaGetSymbolAddress((void**)&w2l, g_w2l);
    cudaGetSymbolAddress((void**)&h1h, g_h1h);     cudaGetSymbolAddress((void**)&h1l, g_h1l);
    cudaGetSymbolAddress((void**)&qkv, g_qkv);     cudaGetSymbolAddress((void**)&x1, g_x1);

    static bool attr_done = false;
    if (!attr_done) {
        cudaFuncSetAttribute(gemm_tc<0>, cudaFuncAttributeMaxDynamicSharedMemorySize, GEMM_SMEM);
        cudaFuncSetAttribute(gemm_tc<1>, cudaFuncAttributeMaxDynamicSharedMemorySize, GEMM_SMEM);
        cudaFuncSetAttribute(gemm_tc<2>, cudaFuncAttributeMaxDynamicSharedMemorySize, GEMM_SMEM);
        cudaFuncSetAttribute(flash_kernel, cudaFuncAttributeMaxDynamicSharedMemorySize, FLASH_SMEM);
        attr_done = true;
    }

    // weight splits (no transpose; QKV fused into [1024][3072])
    wsplit<<<1024, 256>>>(wq, wqkvh, wqkvl, D, 3 * D, 0);
    wsplit<<<1024, 256>>>(wk, wqkvh, wqkvl, D, 3 * D, D);
    wsplit<<<1024, 256>>>(wv, wqkvh, wqkvl, D, 3 * D, 2 * D);
    wsplit<<<1024, 256>>>(wo, woh, wol, D, D, 0);
    wsplit<<<4096, 256>>>(w1, w1h, w1l, D4, D4, 0);
    wsplit<<<4096, 256>>>(w2, w2h, w2l, D, D, 0);

    // LN1 (split output)
    ln_split<<<BT, 256>>>(x, g1, be1, xnh, xnl);

    // fused QKV: [8192,1024] @ [1024,3072] -> qkv fp32
    gemm_tc<0><<<dim3(3 * D / 256, BT / 128), 256, GEMM_SMEM>>>(
        xnh, xnl, wqkvh, wqkvl, nullptr, nullptr, qkv, nullptr, nullptr, BT, 3 * D, D);

    // flash attention -> attn split into xnh/xnl
    flash_kernel<<<dim3(T / 128, H, Bsz), 256, FLASH_SMEM>>>(qkv, xnh, xnl);

    // Wo + bo + residual(x) -> x1
    gemm_tc<1><<<dim3(D / 256, BT / 128), 256, GEMM_SMEM>>>(
        xnh, xnl, woh, wol, bo, x, x1, nullptr, nullptr, BT, D, D);

    // LN2 -> xn split (reused)
    ln_split<<<BT, 256>>>(x1, g2, be2, xnh, xnl);

    // FFN up: relu(xn @ w1 + b1) -> h1 split
    gemm_tc<2><<<dim3(D4 / 256, BT / 128), 256, GEMM_SMEM>>>(
        xnh, xnl, w1h, w1l, b1, nullptr, nullptr, h1h, h1l, BT, D4, D);

    // FFN down: h1 @ w2 + b2 + residual(x1) -> out
    gemm_tc<1><<<dim3(D / 256, BT / 128), 256, GEMM_SMEM>>>(
        h1h, h1l, w2h, w2l, b2, x1, out, nullptr, nullptr, BT, D, D4);
}

// round 5
// speedup vs baseline: 3.0878x; 1.3243x over previous
#include <cuda_runtime.h>
#include <cuda_bf16.h>
#include <cstdint>
#include <math.h>

#define Bsz 4
#define T   2048
#define D   1024
#define H   16
#define HS  64
#define BT  (Bsz*T)      // 8192
#define D4  (4*D)        // 4096

// ======================= scratch ============================================
__device__ __nv_bfloat16 g_xnh[BT*D], g_xnl[BT*D];        // LN out / attn out (reused)
__device__ __nv_bfloat16 g_wqkvh[(size_t)D*3*D], g_wqkvl[(size_t)D*3*D]; // [1024][3072]
__device__ __nv_bfloat16 g_woh[D*D], g_wol[D*D];          // [1024][1024]
__device__ __nv_bfloat16 g_w1h[(size_t)D*D4], g_w1l[(size_t)D*D4];  // [1024][4096]
__device__ __nv_bfloat16 g_w2h[(size_t)D4*D], g_w2l[(size_t)D4*D];  // [4096][1024]
__device__ __nv_bfloat16 g_qkvh[(size_t)BT*3*D], g_qkvl[(size_t)BT*3*D]; // [8192][3072]
__device__ __nv_bfloat16 g_h1h[(size_t)BT*D4], g_h1l[(size_t)BT*D4];
__device__ float g_x1[BT*D];

// ======================= asm helpers ========================================
__device__ __forceinline__ uint32_t smem_u32(const void* p) {
    uint32_t a;
    asm("{ .reg .u64 t; cvta.to.shared.u64 t, %1; cvt.u32.u64 %0, t; }"
        : "=r"(a) : "l"(p));
    return a;
}
__device__ __forceinline__ void cp16(uint32_t s, const void* g) {
    asm volatile("cp.async.cg.shared.global [%0], [%1], 16;" :: "r"(s), "l"(g));
}
#define CP_COMMIT() asm volatile("cp.async.commit_group;" ::: "memory")
#define CP_WAIT(n)  asm volatile("cp.async.wait_group %0;" :: "n"(n) : "memory")

__device__ __forceinline__ void ldsm_x4(uint32_t* r, uint32_t a) {
    asm volatile("ldmatrix.sync.aligned.m8n8.x4.shared.b16 {%0,%1,%2,%3}, [%4];"
                 : "=r"(r[0]), "=r"(r[1]), "=r"(r[2]), "=r"(r[3]) : "r"(a));
}
__device__ __forceinline__ void ldsm_x4t(uint32_t* r, uint32_t a) {
    asm volatile("ldmatrix.sync.aligned.m8n8.x4.trans.shared.b16 {%0,%1,%2,%3}, [%4];"
                 : "=r"(r[0]), "=r"(r[1]), "=r"(r[2]), "=r"(r[3]) : "r"(a));
}
__device__ __forceinline__ void ldsm_x2t(uint32_t* r, uint32_t a) {
    asm volatile("ldmatrix.sync.aligned.m8n8.x2.trans.shared.b16 {%0,%1}, [%2];"
                 : "=r"(r[0]), "=r"(r[1]) : "r"(a));
}
__device__ __forceinline__ void mma_bf16(float* d, const uint32_t* a, const uint32_t* b) {
    asm volatile(
        "mma.sync.aligned.m16n8k16.row.col.f32.bf16.bf16.f32 "
        "{%0,%1,%2,%3}, {%4,%5,%6,%7}, {%8,%9}, {%0,%1,%2,%3};"
        : "+f"(d[0]), "+f"(d[1]), "+f"(d[2]), "+f"(d[3])
        : "r"(a[0]), "r"(a[1]), "r"(a[2]), "r"(a[3]), "r"(b[0]), "r"(b[1]));
}
__device__ __forceinline__ void mma4(float* d, const uint32_t* a, uint32_t b0, uint32_t b1) {
    asm volatile(
        "mma.sync.aligned.m16n8k16.row.col.f32.bf16.bf16.f32 "
        "{%0,%1,%2,%3}, {%4,%5,%6,%7}, {%8,%9}, {%0,%1,%2,%3};"
        : "+f"(d[0]), "+f"(d[1]), "+f"(d[2]), "+f"(d[3])
        : "r"(a[0]), "r"(a[1]), "r"(a[2]), "r"(a[3]), "r"(b0), "r"(b1));
}
__device__ __forceinline__ void split2(float a, float b, uint32_t& hi, uint32_t& lo) {
    __nv_bfloat16 ha = __float2bfloat16(a), hb = __float2bfloat16(b);
    __nv_bfloat16 la = __float2bfloat16(a - __bfloat162float(ha));
    __nv_bfloat16 lb = __float2bfloat16(b - __bfloat162float(hb));
    __nv_bfloat162 h2(ha, hb), l2(la, lb);
    hi = *(uint32_t*)&h2; lo = *(uint32_t*)&l2;
}

// ================= merged weight splits =====================================
__device__ __forceinline__ void wsplit_body(const float* W, __nv_bfloat16* Th,
                                            __nv_bfloat16* Tl, int n_src,
                                            int dst_stride, int col_off, int blk) {
    size_t p4 = ((size_t)blk * 256 + threadIdx.x) * 4;
    float4 w = *(const float4*)(W + p4);
    int k = (int)(p4 / n_src), n = (int)(p4 % n_src);
    size_t o = (size_t)k * dst_stride + col_off + n;
    float vv[4] = {w.x, w.y, w.z, w.w};
    #pragma unroll
    for (int j = 0; j < 4; j += 2) {
        uint32_t hi, lo;
        split2(vv[j], vv[j+1], hi, lo);
        *(uint32_t*)(Th + o + j) = hi;
        *(uint32_t*)(Tl + o + j) = lo;
    }
}
__global__ __launch_bounds__(256)
void wsplit_qkv(const float* __restrict__ wq, const float* __restrict__ wk,
                const float* __restrict__ wv, __nv_bfloat16* __restrict__ Th,
                __nv_bfloat16* __restrict__ Tl) {
    int bid = blockIdx.x;
    if (bid < 1024)      wsplit_body(wq, Th, Tl, D, 3*D, 0,   bid);
    else if (bid < 2048) wsplit_body(wk, Th, Tl, D, 3*D, D,   bid - 1024);
    else                 wsplit_body(wv, Th, Tl, D, 3*D, 2*D, bid - 2048);
}
__global__ __launch_bounds__(256)
void wsplit_rest(const float* __restrict__ wo, const float* __restrict__ w1,
                 const float* __restrict__ w2,
                 __nv_bfloat16* __restrict__ woh, __nv_bfloat16* __restrict__ wol,
                 __nv_bfloat16* __restrict__ w1h, __nv_bfloat16* __restrict__ w1l,
                 __nv_bfloat16* __restrict__ w2h, __nv_bfloat16* __restrict__ w2l) {
    int bid = blockIdx.x;
    if (bid < 1024)      wsplit_body(wo, woh, wol, D,  D,  0, bid);
    else if (bid < 5120) wsplit_body(w1, w1h, w1l, D4, D4, 0, bid - 1024);
    else                 wsplit_body(w2, w2h, w2l, D,  D,  0, bid - 5120);
}

// ================= LayerNorm with fused bf16 hi/lo split ====================
__global__ __launch_bounds__(256)
void ln_split(const float* __restrict__ x, const float* __restrict__ g,
              const float* __restrict__ b, __nv_bfloat16* __restrict__ oh,
              __nv_bfloat16* __restrict__ ol) {
    int row = blockIdx.x;
    int tid = threadIdx.x;
    float4 v4 = ((const float4*)(x + (size_t)row * D))[tid];
    float s  = v4.x + v4.y + v4.z + v4.w;
    float ss = v4.x*v4.x + v4.y*v4.y + v4.z*v4.z + v4.w*v4.w;
    #pragma unroll
    for (int off = 16; off; off >>= 1) {
        s  += __shfl_xor_sync(0xffffffffu, s,  off);
        ss += __shfl_xor_sync(0xffffffffu, ss, off);
    }
    __shared__ float rs[8], rss[8];
    int warp = tid >> 5, lane = tid & 31;
    if (lane == 0) { rs[warp] = s; rss[warp] = ss; }
    __syncthreads();
    float tot = 0.f, tot2 = 0.f;
    #pragma unroll
    for (int i = 0; i < 8; i++) { tot += rs[i]; tot2 += rss[i]; }
    float mu = tot * (1.0f / D);
    float rstd = rsqrtf(tot2 * (1.0f / D) - mu * mu + 1e-5f);
    float4 g4 = ((const float4*)g)[tid];
    float4 b4 = ((const float4*)b)[tid];
    float o[4];
    o[0] = (v4.x - mu) * rstd * g4.x + b4.x;
    o[1] = (v4.y - mu) * rstd * g4.y + b4.y;
    o[2] = (v4.z - mu) * rstd * g4.z + b4.z;
    o[3] = (v4.w - mu) * rstd * g4.w + b4.w;
    size_t base = (size_t)row * D + tid * 4;
    #pragma unroll
    for (int j = 0; j < 4; j += 2) {
        uint32_t hi, lo;
        split2(o[j], o[j+1], hi, lo);
        *(uint32_t*)(oh + base + j) = hi;
        *(uint32_t*)(ol + base + j) = lo;
    }
}

// ================= HMMA bf16x3 GEMM =========================================
// CTA 128x256, K-chunk 32, 3-stage cp.async, 8 warps = 2x4 of 64x64.
// EPI: 1 = +bias+res -> fp32; 2 = relu(+bias) -> bf16 hi/lo; 3 = bf16 hi/lo.
#define STAGES 3
#define AH_OFF 0
#define AL_OFF 10240
#define BH_OFF 20480
#define BL_OFF 36864
#define STG    53248
#define GEMM_SMEM (STAGES * STG)

template<int EPI>
__global__ __launch_bounds__(256, 1)
void gemm_tc(const __nv_bfloat16* __restrict__ Ah, const __nv_bfloat16* __restrict__ Al,
             const __nv_bfloat16* __restrict__ Wh, const __nv_bfloat16* __restrict__ Wl,
             const float* __restrict__ bias, const float* __restrict__ res,
             float* __restrict__ Cf, __nv_bfloat16* __restrict__ Ch,
             __nv_bfloat16* __restrict__ Cl, int M, int N, int K) {
    extern __shared__ char smem[];
    uint32_t sbase = smem_u32(smem);
    const int tid = threadIdx.x;
    const int lane = tid & 31, wid = tid >> 5;
    const int wr = wid >> 2, wc = wid & 3;   // warp tile: rows wr*64, cols wc*64
    const int m0 = blockIdx.y * 128, n0 = blockIdx.x * 256;
    const int nch = K >> 5;

    float acc[4][8][4];
    #pragma unroll
    for (int i = 0; i < 4; i++)
        #pragma unroll
        for (int j = 0; j < 8; j++)
            #pragma unroll
            for (int q = 0; q < 4; q++) acc[i][j][q] = 0.f;

    auto load_stage = [&](int st, int c) {
        uint32_t sb = sbase + st * STG;
        int k0 = c << 5;
        #pragma unroll
        for (int i = 0; i < 2; i++) {         // A: 128 rows x 4 16B-chunks (hi+lo)
            int pos = i * 256 + tid;
            int row = pos >> 2, kc = pos & 3;
            uint32_t so = row * 80 + kc * 16;
            cp16(sb + AH_OFF + so, Ah + (size_t)(m0 + row) * K + k0 + kc * 8);
            cp16(sb + AL_OFF + so, Al + (size_t)(m0 + row) * K + k0 + kc * 8);
        }
        #pragma unroll
        for (int i = 0; i < 4; i++) {         // B: 32 k-rows x 32 16B-chunks (swizzled)
            int pos = i * 256 + tid;
            int krow = pos >> 5, cch = pos & 31;
            uint32_t so = krow * 512 + ((cch ^ (krow & 7)) * 16);
            cp16(sb + BH_OFF + so, Wh + (size_t)(k0 + krow) * N + n0 + cch * 8);
            cp16(sb + BL_OFF + so, Wl + (size_t)(k0 + krow) * N + n0 + cch * 8);
        }
    };

    #pragma unroll
    for (int s = 0; s < STAGES - 1; s++) { load_stage(s, s); CP_COMMIT(); }

    for (int c = 0; c < nch; c++) {
        if (c + STAGES - 1 < nch) load_stage((c + STAGES - 1) % STAGES, c + STAGES - 1);
        CP_COMMIT();
        CP_WAIT(STAGES - 1);
        __syncthreads();

        uint32_t sb = sbase + (c % STAGES) * STG;
        #pragma unroll
        for (int ks = 0; ks < 2; ks++) {
            uint32_t bh[8][2], bl[8][2];
            int kloc = ks * 16 + (lane & 15);
            #pragma unroll
            for (int fn = 0; fn < 8; fn++) {
                int cch = wc * 8 + fn;
                uint32_t byte = kloc * 512 + ((cch ^ (kloc & 7)) * 16);
                ldsm_x2t(bh[fn], sb + BH_OFF + byte);
                ldsm_x2t(bl[fn], sb + BL_OFF + byte);
            }
            #pragma unroll
            for (int fm = 0; fm < 4; fm++) {
                uint32_t ah[4], al[4];
                int mloc = wr * 64 + fm * 16 + (lane & 15);
                uint32_t byte = mloc * 80 + ks * 32 + ((lane >> 4) & 1) * 16;
                ldsm_x4(ah, sb + AH_OFF + byte);
                ldsm_x4(al, sb + AL_OFF + byte);
                #pragma unroll
                for (int fn = 0; fn < 8; fn++) {
                    mma_bf16(acc[fm][fn], ah, bh[fn]);
                    mma_bf16(acc[fm][fn], ah, bl[fn]);
                    mma_bf16(acc[fm][fn], al, bh[fn]);
                }
            }
        }
        __syncthreads();
    }

    // ---- epilogue ----
    int grp = lane >> 2, tg = lane & 3;
    #pragma unroll
    for (int fm = 0; fm < 4; fm++) {
        int r0 = m0 + wr * 64 + fm * 16 + grp;
        #pragma unroll
        for (int fn = 0; fn < 8; fn++) {
            int c0 = n0 + wc * 64 + fn * 8 + tg * 2;
            float* dd = acc[fm][fn];
            #pragma unroll
            for (int half = 0; half < 2; half++) {
                int r = r0 + half * 8;
                float v0 = dd[half * 2 + 0], v1 = dd[half * 2 + 1];
                if (EPI == 1) {
                    const float2 rv = *(const float2*)(res + (size_t)r * N + c0);
                    const float2 bv = *(const float2*)(bias + c0);
                    *(float2*)(Cf + (size_t)r * N + c0) =
                        make_float2(v0 + bv.x + rv.x, v1 + bv.y + rv.y);
                } else if (EPI == 2) {
                    const float2 bv = *(const float2*)(bias + c0);
                    float a0 = fmaxf(v0 + bv.x, 0.f), a1 = fmaxf(v1 + bv.y, 0.f);
                    uint32_t hi, lo;
                    split2(a0, a1, hi, lo);
                    *(uint32_t*)(Ch + (size_t)r * N + c0) = hi;
                    *(uint32_t*)(Cl + (size_t)r * N + c0) = lo;
                } else {  // EPI == 3
                    uint32_t hi, lo;
                    split2(v0, v1, hi, lo);
                    *(uint32_t*)(Ch + (size_t)r * N + c0) = hi;
                    *(uint32_t*)(Cl + (size_t)r * N + c0) = lo;
                }
            }
        }
    }
}

// ================= flash attention: HMMA bf16x3 + fp32 softmax ==============
__device__ __forceinline__ float fexp(float x) {
    float y = fmaxf(x * 1.4426950408889634f, -126.0f);
    float n = rintf(y);
    float t = (y - n) * 0.6931471805599453f;
    float p = fmaf(t, 8.3333333e-3f, 4.1666667e-2f);
    p = fmaf(p, t, 0.166666667f);
    p = fmaf(p, t, 0.5f);
    p = fmaf(p, t, 1.0f);
    p = fmaf(p, t, 1.0f);
    return __int_as_float(((int)n + 127) << 23) * p;
}

// smem: Qh/Ql 16KB each; 2 KV stages of (Kh,Kl,Vh,Vl) 16KB each.
#define FLASH_SMEM (32768 + 2 * 65536)

__global__ __launch_bounds__(256, 1)
void flash_kernel(const __nv_bfloat16* __restrict__ qkvh,
                  const __nv_bfloat16* __restrict__ qkvl,
                  __nv_bfloat16* __restrict__ oh, __nv_bfloat16* __restrict__ ol) {
    extern __shared__ char fsm[];
    uint32_t sb = smem_u32(fsm);
    const int qt = (int)gridDim.x - 1 - (int)blockIdx.x;  // big tiles first
    const int h = blockIdx.y, b = blockIdx.z;
    const int q0 = qt * 128;
    const int tid = threadIdx.x, lane = tid & 31, wid = tid >> 5;
    const int grp = lane >> 2, tg = lane & 3;
    const size_t RS = 3 * D;

    // Q tile load (hi+lo), swizzled rows of 128B
    #pragma unroll
    for (int it = 0; it < 4; it++) {
        int idx = it * 256 + tid;
        int row = idx >> 3, c = idx & 7;
        uint32_t so = row * 128 + ((c ^ (row & 7)) * 16);
        size_t go = (size_t)(b * T + q0 + row) * RS + h * HS + c * 8;
        cp16(sb + so, qkvh + go);
        cp16(sb + 16384 + so, qkvl + go);
    }
    auto load_kv = [&](int st, int kt) {
        uint32_t base = sb + 32768 + st * 65536;
        int k0 = kt * 128;
        #pragma unroll
        for (int it = 0; it < 4; it++) {
            int idx = it * 256 + tid;
            int row = idx >> 3, c = idx & 7;
            uint32_t so = row * 128 + ((c ^ (row & 7)) * 16);
            size_t gk = (size_t)(b * T + k0 + row) * RS + D + h * HS + c * 8;
            size_t gv = gk + D;
            cp16(base + so,         qkvh + gk);
            cp16(base + 16384 + so, qkvl + gk);
            cp16(base + 32768 + so, qkvh + gv);
            cp16(base + 49152 + so, qkvl + gv);
        }
    };
    load_kv(0, 0);
    CP_COMMIT();

    uint32_t qh[4][4], ql[4][4];
    float o[8][4];
    #pragma unroll
    for (int fn = 0; fn < 8; fn++)
        #pragma unroll
        for (int q = 0; q < 4; q++) o[fn][q] = 0.f;
    float m0 = -1e30f, m1 = -1e30f, l0 = 0.f, l1 = 0.f;
    const float scale = 0.03125f;
    const int row0 = q0 + wid * 16 + grp;

    for (int kt = 0; kt <= qt; kt++) {
        if (kt + 1 <= qt) { load_kv((kt + 1) & 1, kt + 1); CP_COMMIT(); CP_WAIT(1); }
        else              { CP_WAIT(0); }
        __syncthreads();
        if (kt == 0) {  // Q fragments into registers (once)
            int mrow = wid * 16 + (lane & 15);
            #pragma unroll
            for (int kf = 0; kf < 4; kf++) {
                int c = kf * 2 + (lane >> 4);
                uint32_t byte = mrow * 128 + ((c ^ (mrow & 7)) * 16);
                ldsm_x4(qh[kf], sb + byte);
                ldsm_x4(ql[kf], sb + 16384 + byte);
            }
        }
        uint32_t kb = sb + 32768 + (kt & 1) * 65536;

        // ---- S = Q K^T (bf16x3) ----
        float s[16][4];
        #pragma unroll
        for (int f = 0; f < 16; f++)
            #pragma unroll
            for (int q = 0; q < 4; q++) s[f][q] = 0.f;
        #pragma unroll
        for (int nt = 0; nt < 8; nt++) {
            int krow = nt * 16 + (lane & 15);
            #pragma unroll
            for (int kf = 0; kf < 4; kf++) {
                uint32_t kh4[4], kl4[4];
                int c = kf * 2 + (lane >> 4);
                uint32_t byte = krow * 128 + ((c ^ (krow & 7)) * 16);
                ldsm_x4(kh4, kb + byte);
                ldsm_x4(kl4, kb + 16384 + byte);
                mma4(s[nt*2],   qh[kf], kh4[0], kh4[2]);
                mma4(s[nt*2],   qh[kf], kl4[0], kl4[2]);
                mma4(s[nt*2],   ql[kf], kh4[0], kh4[2]);
                mma4(s[nt*2+1], qh[kf], kh4[1], kh4[3]);
                mma4(s[nt*2+1], qh[kf], kl4[1], kl4[3]);
                mma4(s[nt*2+1], ql[kf], kh4[1], kh4[3]);
            }
        }

        // ---- online softmax (fp32, quad-shuffles) ----
        const bool diag = (kt == qt);
        const int k0 = kt * 128;
        float mx0 = -1e30f, mx1 = -1e30f;
        #pragma unroll
        for (int f = 0; f < 16; f++) {
            int c0 = k0 + f * 8 + tg * 2;
            s[f][0] *= scale; s[f][1] *= scale; s[f][2] *= scale; s[f][3] *= scale;
            if (diag) {
                if (c0     > row0)     s[f][0] = -1e30f;
                if (c0 + 1 > row0)     s[f][1] = -1e30f;
                if (c0     > row0 + 8) s[f][2] = -1e30f;
                if (c0 + 1 > row0 + 8) s[f][3] = -1e30f;
            }
            mx0 = fmaxf(mx0, fmaxf(s[f][0], s[f][1]));
            mx1 = fmaxf(mx1, fmaxf(s[f][2], s[f][3]));
        }
        mx0 = fmaxf(mx0, __shfl_xor_sync(0xffffffffu, mx0, 1));
        mx0 = fmaxf(mx0, __shfl_xor_sync(0xffffffffu, mx0, 2));
        mx1 = fmaxf(mx1, __shfl_xor_sync(0xffffffffu, mx1, 1));
        mx1 = fmaxf(mx1, __shfl_xor_sync(0xffffffffu, mx1, 2));
        float mn0 = fmaxf(m0, mx0), mn1 = fmaxf(m1, mx1);
        float al0 = fexp(m0 - mn0), al1 = fexp(m1 - mn1);
        float ls0 = 0.f, ls1 = 0.f;
        #pragma unroll
        for (int f = 0; f < 16; f++) {
            s[f][0] = fexp(s[f][0] - mn0); s[f][1] = fexp(s[f][1] - mn0);
            s[f][2] = fexp(s[f][2] - mn1); s[f][3] = fexp(s[f][3] - mn1);
            ls0 += s[f][0] + s[f][1];
            ls1 += s[f][2] + s[f][3];
        }
        ls0 += __shfl_xor_sync(0xffffffffu, ls0, 1);
        ls0 += __shfl_xor_sync(0xffffffffu, ls0, 2);
        ls1 += __shfl_xor_sync(0xffffffffu, ls1, 1);
        ls1 += __shfl_xor_sync(0xffffffffu, ls1, 2);
        l0 = l0 * al0 + ls0; l1 = l1 * al1 + ls1;
        m0 = mn0; m1 = mn1;
        #pragma unroll
        for (int fn = 0; fn < 8; fn++) {
            o[fn][0] *= al0; o[fn][1] *= al0; o[fn][2] *= al1; o[fn][3] *= al1;
        }

        // ---- pack P into A-fragments (bf16 hi/lo) ----
        uint32_t ph[8][4], pl[8][4];
        #pragma unroll
        for (int kf2 = 0; kf2 < 8; kf2++) {
            float* f0 = s[kf2 * 2];
            float* f1 = s[kf2 * 2 + 1];
            split2(f0[0], f0[1], ph[kf2][0], pl[kf2][0]);
            split2(f0[2], f0[3], ph[kf2][1], pl[kf2][1]);
            split2(f1[0], f1[1], ph[kf2][2], pl[kf2][2]);
            split2(f1[2], f1[3], ph[kf2][3], pl[kf2][3]);
        }

        // ---- O += P V (bf16x3) ----
        uint32_t vbh = kb + 32768, vbl = kb + 49152;
        #pragma unroll
        for (int kf2 = 0; kf2 < 8; kf2++) {
            int vrow = kf2 * 16 + (lane & 15);
            #pragma unroll
            for (int fp = 0; fp < 4; fp++) {
                int c = fp * 2 + (lane >> 4);
                uint32_t byte = vrow * 128 + ((c ^ (vrow & 7)) * 16);
                uint32_t vh4[4], vl4[4];
                ldsm_x4t(vh4, vbh + byte);
                ldsm_x4t(vl4, vbl + byte);
                mma4(o[fp*2],   ph[kf2], vh4[0], vh4[1]);
                mma4(o[fp*2],   ph[kf2], vl4[0], vl4[1]);
                mma4(o[fp*2],   pl[kf2], vh4[0], vh4[1]);
                mma4(o[fp*2+1], ph[kf2], vh4[2], vh4[3]);
                mma4(o[fp*2+1], ph[kf2], vl4[2], vl4[3]);
                mma4(o[fp*2+1], pl[kf2], vh4[2], vh4[3]);
            }
        }
        __syncthreads();
    }

    // ---- epilogue: normalize + bf16 hi/lo split ----
    float inv0 = 1.0f / l0, inv1 = 1.0f / l1;
    size_t r0g = (size_t)(b * T + row0) * D + h * HS;
    size_t r1g = r0g + (size_t)8 * D;
    #pragma unroll
    for (int fn = 0; fn < 8; fn++) {
        int col = fn * 8 + tg * 2;
        uint32_t hi, lo;
        split2(o[fn][0] * inv0, o[fn][1] * inv0, hi, lo);
        *(uint32_t*)(oh + r0g + col) = hi;
        *(uint32_t*)(ol + r0g + col) = lo;
        split2(o[fn][2] * inv1, o[fn][3] * inv1, hi, lo);
        *(uint32_t*)(oh + r1g + col) = hi;
        *(uint32_t*)(ol + r1g + col) = lo;
    }
}

// ================= launch ===================================================
extern "C" void kernel_launch(void* const* d_in, const int* in_sizes, int n_in,
                              void* d_out, int out_size) {
    const float* x   = (const float*)d_in[0];
    const float* wq  = (const float*)d_in[1];
    const float* wk  = (const float*)d_in[2];
    const float* wv  = (const float*)d_in[3];
    const float* wo  = (const float*)d_in[4];
    const float* bo  = (const float*)d_in[5];
    const float* w1  = (const float*)d_in[6];
    const float* b1  = (const float*)d_in[7];
    const float* w2  = (const float*)d_in[8];
    const float* b2  = (const float*)d_in[9];
    const float* g1  = (const float*)d_in[10];
    const float* be1 = (const float*)d_in[11];
    const float* g2  = (const float*)d_in[12];
    const float* be2 = (const float*)d_in[13];
    float* out = (float*)d_out;

    __nv_bfloat16 *xnh, *xnl, *wqkvh, *wqkvl, *woh, *wol, *w1h, *w1l, *w2h, *w2l;
    __nv_bfloat16 *qkvh, *qkvl, *h1h, *h1l;
    float *x1;
    cudaGetSymbolAddress((void**)&xnh, g_xnh);     cudaGetSymbolAddress((void**)&xnl, g_xnl);
    cudaGetSymbolAddress((void**)&wqkvh, g_wqkvh); cudaGetSymbolAddress((void**)&wqkvl, g_wqkvl);
    cudaGetSymbolAddress((void**)&woh, g_woh);     cudaGetSymbolAddress((void**)&wol, g_wol);
    cudaGetSymbolAddress((void**)&w1h, g_w1h);     cudaGetSymbolAddress((void**)&w1l, g_w1l);
    cudaGetSymbolAddress((void**)&w2h, g_w2h);     cudaGetSymbolAddress((void**)&w2l, g_w2l);
    cudaGetSymbolAddress((void**)&qkvh, g_qkvh);   cudaGetSymbolAddress((void**)&qkvl, g_qkvl);
    cudaGetSymbolAddress((void**)&h1h, g_h1h);     cudaGetSymbolAddress((void**)&h1l, g_h1l);
    cudaGetSymbolAddress((void**)&x1, g_x1);

    static bool attr_done = false;
    if (!attr_done) {
        cudaFuncSetAttribute(gemm_tc<1>, cudaFuncAttributeMaxDynamicSharedMemorySize, GEMM_SMEM);
        cudaFuncSetAttribute(gemm_tc<2>, cudaFuncAttributeMaxDynamicSharedMemorySize, GEMM_SMEM);
        cudaFuncSetAttribute(gemm_tc<3>, cudaFuncAttributeMaxDynamicSharedMemorySize, GEMM_SMEM);
        cudaFuncSetAttribute(flash_kernel, cudaFuncAttributeMaxDynamicSharedMemorySize, FLASH_SMEM);
        attr_done = true;
    }

    // 1-2: weight splits
    wsplit_qkv<<<3072, 256>>>(wq, wk, wv, wqkvh, wqkvl);
    wsplit_rest<<<9216, 256>>>(wo, w1, w2, woh, wol, w1h, w1l, w2h, w2l);

    // 3: LN1
    ln_split<<<BT, 256>>>(x, g1, be1, xnh, xnl);

    // 4: fused QKV -> bf16 hi/lo  [8192,3072]
    gemm_tc<3><<<dim3(3 * D / 256, BT / 128), 256, GEMM_SMEM>>>(
        xnh, xnl, wqkvh, wqkvl, nullptr, nullptr, nullptr, qkvh, qkvl, BT, 3 * D, D);

    // 5: flash attention (HMMA) -> attn hi/lo into xnh/xnl
    flash_kernel<<<dim3(T / 128, H, Bsz), 256, FLASH_SMEM>>>(qkvh, qkvl, xnh, xnl);

    // 6: Wo + bo + residual(x) -> x1   (ncu -s 5 profiles this launch)
    gemm_tc<1><<<dim3(D / 256, BT / 128), 256, GEMM_SMEM>>>(
        xnh, xnl, woh, wol, bo, x, x1, nullptr, nullptr, BT, D, D);

    // 7: LN2
    ln_split<<<BT, 256>>>(x1, g2, be2, xnh, xnl);

    // 8: FFN up: relu(xn @ w1 + b1) -> h1 hi/lo
    gemm_tc<2><<<dim3(D4 / 256, BT / 128), 256, GEMM_SMEM>>>(
        xnh, xnl, w1h, w1l, b1, nullptr, nullptr, h1h, h1l, BT, D4, D);

    // 9: FFN down: h1 @ w2 + b2 + residual(x1) -> out
    gemm_tc<1><<<dim3(D / 256, BT / 128), 256, GEMM_SMEM>>>(
        h1h, h1l, w2h, w2l, b2, x1, out, nullptr, nullptr, BT, D, D4);
}